// round 4
// baseline (speedup 1.0000x reference)
#include <cuda_runtime.h>
#include <cuda_bf16.h>
#include <math.h>
#include <stdint.h>

#define BB     16
#define NN     512
#define DD     1024
#define EE     2048
#define SS     128
#define FF     4224
#define MTOT   8192

// ---------------- scratch ----------------------------------------------------
__device__ __nv_bfloat16 g_xnh[(size_t)MTOT * DD];
__device__ __nv_bfloat16 g_xnl[(size_t)MTOT * DD];
__device__ __nv_bfloat16 g_wuvh[(size_t)FF * DD];
__device__ __nv_bfloat16 g_wuvl[(size_t)FF * DD];
__device__ float         g_uv [(size_t)MTOT * FF];
__device__ __nv_bfloat16 g_vth[(size_t)BB * EE * NN];
__device__ __nv_bfloat16 g_vtl[(size_t)BB * EE * NN];
__device__ float         g_q  [(size_t)MTOT * SS];
__device__ float         g_k  [(size_t)MTOT * SS];
__device__ __nv_bfloat16 g_kerh[(size_t)BB * NN * NN];
__device__ __nv_bfloat16 g_kerl[(size_t)BB * NN * NN];
__device__ __nv_bfloat16 g_gh [(size_t)MTOT * EE];
__device__ __nv_bfloat16 g_gl [(size_t)MTOT * EE];
__device__ __nv_bfloat16 g_owh[(size_t)DD * EE];
__device__ __nv_bfloat16 g_owl[(size_t)DD * EE];

// ---------------- helpers -----------------------------------------------------
__device__ __forceinline__ uint32_t smem_u32(const void* p) {
    uint32_t a;
    asm("{ .reg .u64 t; cvta.to.shared.u64 t, %1; cvt.u32.u64 %0, t; }" : "=r"(a) : "l"(p));
    return a;
}
__device__ __forceinline__ void ldmx4(uint32_t* r, uint32_t a) {
    asm volatile("ldmatrix.sync.aligned.m8n8.x4.shared.b16 {%0,%1,%2,%3}, [%4];"
        : "=r"(r[0]), "=r"(r[1]), "=r"(r[2]), "=r"(r[3]) : "r"(a));
}
__device__ __forceinline__ void mma16816(float* c, const uint32_t* a,
                                         uint32_t b0, uint32_t b1) {
    asm volatile("mma.sync.aligned.m16n8k16.row.col.f32.bf16.bf16.f32 "
        "{%0,%1,%2,%3}, {%4,%5,%6,%7}, {%8,%9}, {%0,%1,%2,%3};"
        : "+f"(c[0]), "+f"(c[1]), "+f"(c[2]), "+f"(c[3])
        : "r"(a[0]), "r"(a[1]), "r"(a[2]), "r"(a[3]), "r"(b0), "r"(b1));
}
__device__ __forceinline__ void cp16(uint32_t dst, const void* src) {
    asm volatile("cp.async.cg.shared.global [%0], [%1], 16;" :: "r"(dst), "l"(src) : "memory");
}
#define CP_COMMIT() asm volatile("cp.async.commit_group;" ::: "memory")
#define CP_WAIT1()  asm volatile("cp.async.wait_group 1;"  ::: "memory")
#define CP_WAIT0()  asm volatile("cp.async.wait_group 0;"  ::: "memory")

// stage layout: A-hi 32K | A-lo 32K | B-hi 16K | B-lo 16K  = 96 KB
#define STAGE_BYTES 98304
#define OFF_AH 0
#define OFF_AL 32768
#define OFF_BH 65536
#define OFF_BL 81920
#define SMEM_BYTES  (2 * STAGE_BYTES)

// tile loaders: K-chunk = 64 bf16 = 128 bytes per row, SW128-swizzled.
__device__ __forceinline__ void ld_tile256(uint32_t dst, const __nv_bfloat16* src,
                                           int ld_elem, size_t kb0, int tid) {
    const char* sb = (const char*)src + kb0;
#pragma unroll
    for (int it = 0; it < 8; ++it) {
        int L = tid * 16 + it * 4096;
        int row = L >> 7, kb = L & 127;
        cp16(dst + (L ^ ((L >> 3) & 0x70)),
             sb + (size_t)row * ((size_t)ld_elem * 2) + kb);
    }
}
__device__ __forceinline__ void ld_tile128(uint32_t dst, const __nv_bfloat16* src,
                                           int ld_elem, size_t kb0, int tid) {
    const char* sb = (const char*)src + kb0;
#pragma unroll
    for (int it = 0; it < 4; ++it) {
        int L = tid * 16 + it * 4096;
        int row = L >> 7, kb = L & 127;
        cp16(dst + (L ^ ((L >> 3) & 0x70)),
             sb + (size_t)row * ((size_t)ld_elem * 2) + kb);
    }
}

// ---------------- bf16-split MMA GEMM core ------------------------------------
// C(256x128 fp32) = A*B^T; A 256xK (K-major, lda), B 128xK (K-major, ldb).
// 8 warps as 4(M) x 2(N); warp tile 64x64. Epilogue f(row, col, val), tile-rel.
template <class F>
__device__ __forceinline__ void mma_gemm(
    const __nv_bfloat16* __restrict__ Ah, const __nv_bfloat16* __restrict__ Al, int lda,
    const __nv_bfloat16* __restrict__ Bh, const __nv_bfloat16* __restrict__ Bl, int ldb,
    int K, F f)
{
    extern __shared__ char smem[];
    const uint32_t sbase = smem_u32(smem);
    const int tid = threadIdx.x;
    const int lane = tid & 31;
    const int wid = tid >> 5;
    const int wm = wid >> 1, wn = wid & 1;

    float c[4][8][4];
#pragma unroll
    for (int i = 0; i < 4; ++i)
#pragma unroll
        for (int j = 0; j < 8; ++j)
#pragma unroll
            for (int e = 0; e < 4; ++e) c[i][j][e] = 0.f;

    const int NCH = K >> 6;
    const int lhalf = (lane >> 4) << 4;   // 0 or 16 (byte half within 32B k-step)
    const int arow  = wm * 64 + (lane & 15);
    const int brow  = wn * 64 + (lane & 15);

#define LOAD_CHUNK(CC)                                                        \
    {                                                                         \
        uint32_t st_ = sbase + ((CC) & 1) * STAGE_BYTES;                      \
        size_t kb0_ = (size_t)(CC) * 128;                                     \
        ld_tile256(st_ + OFF_AH, Ah, lda, kb0_, tid);                         \
        ld_tile256(st_ + OFF_AL, Al, lda, kb0_, tid);                         \
        ld_tile128(st_ + OFF_BH, Bh, ldb, kb0_, tid);                         \
        ld_tile128(st_ + OFF_BL, Bl, ldb, kb0_, tid);                         \
    }

    LOAD_CHUNK(0);
    CP_COMMIT();

    for (int cc = 0; cc < NCH; ++cc) {
        if (cc + 1 < NCH) {
            LOAD_CHUNK(cc + 1);
            CP_COMMIT();
            CP_WAIT1();
        } else {
            CP_WAIT0();
        }
        __syncthreads();

        const uint32_t st = sbase + (cc & 1) * STAGE_BYTES;
#pragma unroll
        for (int ks = 0; ks < 4; ++ks) {
            const int kb = ks * 32 + lhalf;
            uint32_t ah[4][4], al[4][4];
#pragma unroll
            for (int mt = 0; mt < 4; ++mt) {
                uint32_t off = (uint32_t)(arow + mt * 16) * 128 + kb;
                off ^= (off >> 3) & 0x70;
                ldmx4(ah[mt], st + OFF_AH + off);
                ldmx4(al[mt], st + OFF_AL + off);
            }
#pragma unroll
            for (int np = 0; np < 4; ++np) {
                uint32_t bh[4], bl[4];
                uint32_t off = (uint32_t)(brow + np * 16) * 128 + kb;
                off ^= (off >> 3) & 0x70;
                ldmx4(bh, st + OFF_BH + off);
                ldmx4(bl, st + OFF_BL + off);
#pragma unroll
                for (int mt = 0; mt < 4; ++mt) {
                    float* c0 = c[mt][np * 2 + 0];
                    float* c1 = c[mt][np * 2 + 1];
                    mma16816(c0, ah[mt], bh[0], bh[2]);
                    mma16816(c0, ah[mt], bl[0], bl[2]);
                    mma16816(c0, al[mt], bh[0], bh[2]);
                    mma16816(c1, ah[mt], bh[1], bh[3]);
                    mma16816(c1, ah[mt], bl[1], bl[3]);
                    mma16816(c1, al[mt], bh[1], bh[3]);
                }
            }
        }
        __syncthreads();
    }
#undef LOAD_CHUNK

    const int gID = lane >> 2, tg = lane & 3;
#pragma unroll
    for (int mt = 0; mt < 4; ++mt)
#pragma unroll
        for (int j = 0; j < 8; ++j) {
            int row = wm * 64 + mt * 16 + gID;
            int col = wn * 64 + j * 8 + tg * 2;
            f(row,     col,     c[mt][j][0]);
            f(row,     col + 1, c[mt][j][1]);
            f(row + 8, col,     c[mt][j][2]);
            f(row + 8, col + 1, c[mt][j][3]);
        }
}

// ---------------- LayerNorm -> split bf16 -------------------------------------
__global__ __launch_bounds__(256) void ln_kernel(const float* __restrict__ x,
                                                 const float* __restrict__ w,
                                                 const float* __restrict__ b)
{
    int row = blockIdx.x;
    int tid = threadIdx.x;
    float4 v = ((const float4*)(x + (size_t)row * DD))[tid];
    float s  = v.x + v.y + v.z + v.w;
    float ss = v.x*v.x + v.y*v.y + v.z*v.z + v.w*v.w;
#pragma unroll
    for (int o = 16; o; o >>= 1) {
        s  += __shfl_xor_sync(0xffffffffu, s , o);
        ss += __shfl_xor_sync(0xffffffffu, ss, o);
    }
    __shared__ float sh_s[8], sh_ss[8];
    int warp = tid >> 5;
    if ((tid & 31) == 0) { sh_s[warp] = s; sh_ss[warp] = ss; }
    __syncthreads();
    if (tid == 0) {
        float ts = 0.f, tss = 0.f;
#pragma unroll
        for (int i = 0; i < 8; ++i) { ts += sh_s[i]; tss += sh_ss[i]; }
        sh_s[0] = ts; sh_ss[0] = tss;
    }
    __syncthreads();
    float mean = sh_s[0] * (1.0f / DD);
    float var  = sh_ss[0] * (1.0f / DD) - mean * mean;
    float rs   = rsqrtf(var + 1e-5f);
    float4 wv = ((const float4*)w)[tid];
    float4 bv = ((const float4*)b)[tid];
    float o0 = (v.x - mean) * rs * wv.x + bv.x;
    float o1 = (v.y - mean) * rs * wv.y + bv.y;
    float o2 = (v.z - mean) * rs * wv.z + bv.z;
    float o3 = (v.w - mean) * rs * wv.w + bv.w;
    size_t eb = (size_t)row * DD + tid * 4;
    __nv_bfloat16 h0 = __float2bfloat16(o0), h1 = __float2bfloat16(o1);
    __nv_bfloat16 h2 = __float2bfloat16(o2), h3 = __float2bfloat16(o3);
    __nv_bfloat162 hA; hA.x = h0; hA.y = h1;
    __nv_bfloat162 hB; hB.x = h2; hB.y = h3;
    ((__nv_bfloat162*)(g_xnh + eb))[0] = hA;
    ((__nv_bfloat162*)(g_xnh + eb))[1] = hB;
    __nv_bfloat162 lA, lB;
    lA.x = __float2bfloat16(o0 - __bfloat162float(h0));
    lA.y = __float2bfloat16(o1 - __bfloat162float(h1));
    lB.x = __float2bfloat16(o2 - __bfloat162float(h2));
    lB.y = __float2bfloat16(o3 - __bfloat162float(h3));
    ((__nv_bfloat162*)(g_xnl + eb))[0] = lA;
    ((__nv_bfloat162*)(g_xnl + eb))[1] = lB;
}

// ---------------- fp32 -> bf16 hi/lo split ------------------------------------
__global__ __launch_bounds__(256) void split_kernel(const float* __restrict__ s,
                                                    __nv_bfloat16* __restrict__ h,
                                                    __nv_bfloat16* __restrict__ l,
                                                    int n4)
{
    int i = blockIdx.x * blockDim.x + threadIdx.x;
    if (i >= n4) return;
    float4 v = ((const float4*)s)[i];
    __nv_bfloat16 h0 = __float2bfloat16(v.x), h1 = __float2bfloat16(v.y);
    __nv_bfloat16 h2 = __float2bfloat16(v.z), h3 = __float2bfloat16(v.w);
    __nv_bfloat162 hA; hA.x = h0; hA.y = h1;
    __nv_bfloat162 hB; hB.x = h2; hB.y = h3;
    ((__nv_bfloat162*)h)[2 * i]     = hA;
    ((__nv_bfloat162*)h)[2 * i + 1] = hB;
    __nv_bfloat162 lA, lB;
    lA.x = __float2bfloat16(v.x - __bfloat162float(h0));
    lA.y = __float2bfloat16(v.y - __bfloat162float(h1));
    lB.x = __float2bfloat16(v.z - __bfloat162float(h2));
    lB.y = __float2bfloat16(v.w - __bfloat162float(h3));
    ((__nv_bfloat162*)l)[2 * i]     = lA;
    ((__nv_bfloat162*)l)[2 * i + 1] = lB;
}

// ---------------- GEMM1: uv = silu(xn @ uv_w^T + uv_b) -------------------------
__global__ __launch_bounds__(256, 1) void gemm_uv_mma(const float* __restrict__ uv_b)
{
    const int m0 = blockIdx.y * 256, n0 = blockIdx.x * 128;
    mma_gemm(g_xnh + (size_t)m0 * DD, g_xnl + (size_t)m0 * DD, DD,
             g_wuvh + (size_t)n0 * DD, g_wuvl + (size_t)n0 * DD, DD, DD,
        [&](int r, int cidx, float v) {
            int row = m0 + r, col = n0 + cidx;
            float t = v + uv_b[col];
            g_uv[(size_t)row * FF + col] = t / (1.f + expf(-t));
        });
}

// ---------------- V transpose + split: vt[bt][e][n] -----------------------------
__global__ __launch_bounds__(256) void splitv_kernel()
{
    __shared__ float s[32][33];
    const int bt = blockIdx.z;
    const int k0 = blockIdx.y * 32, n0 = blockIdx.x * 32;
    const int tx = threadIdx.x, ty = threadIdx.y;   // (32, 8)
#pragma unroll
    for (int i = 0; i < 4; ++i) {
        int k = k0 + ty + i * 8;
        s[ty + i * 8][tx] = g_uv[((size_t)bt * NN + k) * FF + EE + n0 + tx];
    }
    __syncthreads();
#pragma unroll
    for (int i = 0; i < 4; ++i) {
        int n = n0 + ty + i * 8;
        float v = s[tx][ty + i * 8];
        __nv_bfloat16 h = __float2bfloat16(v);
        __nv_bfloat16 l = __float2bfloat16(v - __bfloat162float(h));
        size_t off = ((size_t)bt * EE + n) * NN + k0 + tx;
        g_vth[off] = h;
        g_vtl[off] = l;
    }
}

// ---------------- gamma/beta + RoPE -> q, k ------------------------------------
__global__ void rope_kernel(const float* __restrict__ gamma,
                            const float* __restrict__ beta)
{
    const int row = blockIdx.x;
    const int s   = threadIdx.x;       // 0..63
    const int n   = row & (NN - 1);
    const float* base = g_uv + (size_t)row * FF + 2 * EE;
    const float b1 = base[s];
    const float b2 = base[s + 64];
    const float inv_freq = powf(10000.0f, (float)s * (1.0f / 64.0f));
    const float arg = (float)n * inv_freq;
    const float sn = sinf(arg);
    const float cs = cosf(arg);
#pragma unroll
    for (int h = 0; h < 2; ++h) {
        const float x1 = b1 * gamma[h * SS + s]      + beta[h * SS + s];
        const float x2 = b2 * gamma[h * SS + s + 64] + beta[h * SS + s + 64];
        float* dst = (h == 0 ? g_q : g_k) + (size_t)row * SS;
        dst[s]      = x1 * cs - x2 * sn;
        dst[s + 64] = x2 * cs + x1 * sn;
    }
}

// ---------------- qk SGEMM (fp32) + bias + relu^2 -> ker split ------------------
__device__ __forceinline__ void gemm_abt_f32(const float* __restrict__ A,
                                             const float* __restrict__ B_,
                                             int K, int lda, int ldb,
                                             float acc[8][8])
{
    __shared__ float As[8][128];
    __shared__ float Bs[8][128];
    const int tid  = threadIdx.x;
    const int tx   = tid & 15, ty = tid >> 4;
    const int lrow = tid >> 1;
    const int lcol = (tid & 1) << 2;
    const float* Ap = A  + (size_t)lrow * lda + lcol;
    const float* Bp = B_ + (size_t)lrow * ldb + lcol;
#pragma unroll
    for (int i = 0; i < 8; ++i)
#pragma unroll
        for (int j = 0; j < 8; ++j) acc[i][j] = 0.f;
    for (int k0 = 0; k0 < K; k0 += 8) {
        float4 a4 = *(const float4*)(Ap + k0);
        float4 b4 = *(const float4*)(Bp + k0);
        __syncthreads();
        As[lcol+0][lrow] = a4.x; As[lcol+1][lrow] = a4.y;
        As[lcol+2][lrow] = a4.z; As[lcol+3][lrow] = a4.w;
        Bs[lcol+0][lrow] = b4.x; Bs[lcol+1][lrow] = b4.y;
        Bs[lcol+2][lrow] = b4.z; Bs[lcol+3][lrow] = b4.w;
        __syncthreads();
#pragma unroll
        for (int k = 0; k < 8; ++k) {
            float ar[8], br[8];
            *(float4*)(ar)     = *(const float4*)(&As[k][ty*8]);
            *(float4*)(ar + 4) = *(const float4*)(&As[k][ty*8 + 4]);
            *(float4*)(br)     = *(const float4*)(&Bs[k][tx*8]);
            *(float4*)(br + 4) = *(const float4*)(&Bs[k][tx*8 + 4]);
#pragma unroll
            for (int i = 0; i < 8; ++i)
#pragma unroll
                for (int j = 0; j < 8; ++j)
                    acc[i][j] = fmaf(ar[i], br[j], acc[i][j]);
        }
    }
}

__global__ __launch_bounds__(256) void qk_kernel(const float* __restrict__ w_rel)
{
    float acc[8][8];
    const int bt = blockIdx.z;
    const int m0 = blockIdx.y * 128, n0 = blockIdx.x * 128;
    gemm_abt_f32(g_q + ((size_t)bt * NN + m0) * SS,
                 g_k + ((size_t)bt * NN + n0) * SS, SS, SS, SS, acc);
    const int tx = threadIdx.x & 15, ty = threadIdx.x >> 4;
#pragma unroll
    for (int i = 0; i < 8; ++i) {
        const int row = m0 + ty * 8 + i;
#pragma unroll
        for (int j = 0; j < 8; ++j) {
            const int col = n0 + tx * 8 + j;
            float v = acc[i][j] * (1.0f / 512.0f) + w_rel[col - row + 511];
            float r = fmaxf(v, 0.f);
            float kv = r * r;
            __nv_bfloat16 h = __float2bfloat16(kv);
            size_t idx = ((size_t)bt * NN + row) * NN + col;
            g_kerh[idx] = h;
            g_kerl[idx] = __float2bfloat16(kv - __bfloat162float(h));
        }
    }
}

// ---------------- kv: g = (ker @ V) * u  ---------------------------------------
__global__ __launch_bounds__(256, 1) void kv_mma()
{
    const int bt = blockIdx.z;
    const int m0 = blockIdx.y * 256, n0 = blockIdx.x * 128;
    const size_t rbase = (size_t)bt * NN;
    mma_gemm(g_kerh + (rbase + m0) * NN, g_kerl + (rbase + m0) * NN, NN,
             g_vth + ((size_t)bt * EE + n0) * NN,
             g_vtl + ((size_t)bt * EE + n0) * NN, NN, NN,
        [&](int r, int cidx, float v) {
            size_t grow = rbase + m0 + r;
            int col = n0 + cidx;
            float g = g_uv[grow * FF + col] * v;
            __nv_bfloat16 h = __float2bfloat16(g);
            g_gh[grow * EE + col] = h;
            g_gl[grow * EE + col] = __float2bfloat16(g - __bfloat162float(h));
        });
}

// ---------------- out = g @ o_w^T + o_b + shortcut ------------------------------
__global__ __launch_bounds__(256, 1) void out_mma(const float* __restrict__ o_b,
                                                  const float* __restrict__ x,
                                                  float* __restrict__ out)
{
    const int m0 = blockIdx.y * 256, n0 = blockIdx.x * 128;
    mma_gemm(g_gh + (size_t)m0 * EE, g_gl + (size_t)m0 * EE, EE,
             g_owh + (size_t)n0 * EE, g_owl + (size_t)n0 * EE, EE, EE,
        [&](int r, int cidx, float v) {
            int row = m0 + r, col = n0 + cidx;
            out[(size_t)row * DD + col] =
                v + o_b[col] + x[(size_t)row * DD + col];
        });
}

// ---------------- launch --------------------------------------------------------
extern "C" void kernel_launch(void* const* d_in, const int* in_sizes, int n_in,
                              void* d_out, int out_size)
{
    const float* x     = (const float*)d_in[0];
    const float* ln_w  = (const float*)d_in[1];
    const float* ln_b  = (const float*)d_in[2];
    const float* uv_w  = (const float*)d_in[3];
    const float* uv_b  = (const float*)d_in[4];
    const float* gamma = (const float*)d_in[5];
    const float* beta  = (const float*)d_in[6];
    const float* o_w   = (const float*)d_in[7];
    const float* o_b   = (const float*)d_in[8];
    const float* w_rel = (const float*)d_in[9];
    float* out = (float*)d_out;

    cudaFuncSetAttribute(gemm_uv_mma, cudaFuncAttributeMaxDynamicSharedMemorySize, SMEM_BYTES);
    cudaFuncSetAttribute(kv_mma,      cudaFuncAttributeMaxDynamicSharedMemorySize, SMEM_BYTES);
    cudaFuncSetAttribute(out_mma,     cudaFuncAttributeMaxDynamicSharedMemorySize, SMEM_BYTES);

    __nv_bfloat16 *wuvh, *wuvl, *owh, *owl;
    cudaGetSymbolAddress((void**)&wuvh, g_wuvh);
    cudaGetSymbolAddress((void**)&wuvl, g_wuvl);
    cudaGetSymbolAddress((void**)&owh,  g_owh);
    cudaGetSymbolAddress((void**)&owl,  g_owl);

    ln_kernel<<<MTOT, 256>>>(x, ln_w, ln_b);
    split_kernel<<<(FF * DD / 4 + 255) / 256, 256>>>(uv_w, wuvh, wuvl, FF * DD / 4);
    split_kernel<<<(DD * EE / 4 + 255) / 256, 256>>>(o_w, owh, owl, DD * EE / 4);
    gemm_uv_mma<<<dim3(FF / 128, MTOT / 256), 256, SMEM_BYTES>>>(uv_b);
    splitv_kernel<<<dim3(EE / 32, NN / 32, BB), dim3(32, 8)>>>();
    rope_kernel<<<MTOT, 64>>>(gamma, beta);
    qk_kernel<<<dim3(NN / 128, NN / 128, BB), 256>>>(w_rel);
    kv_mma<<<dim3(EE / 128, NN / 256, BB), 256, SMEM_BYTES>>>();
    out_mma<<<dim3(DD / 128, MTOT / 256), 256, SMEM_BYTES>>>(o_b, x, out);
}

// round 5
// speedup vs baseline: 1.3478x; 1.3478x over previous
#include <cuda_runtime.h>
#include <cuda_fp16.h>
#include <math.h>
#include <stdint.h>

#define BB     16
#define NN     512
#define DD     1024
#define EE     2048
#define SS     128
#define FF     4224
#define MTOT   8192

// ---------------- scratch ----------------------------------------------------
__device__ __half g_xnh[(size_t)MTOT * DD];
__device__ __half g_xnl[(size_t)MTOT * DD];
__device__ __half g_wuv[(size_t)FF * DD];
__device__ float  g_uv [(size_t)MTOT * FF];
__device__ __half g_vt [(size_t)BB * EE * NN];
__device__ float  g_q  [(size_t)MTOT * SS];
__device__ float  g_k  [(size_t)MTOT * SS];
__device__ __half g_kerh[(size_t)BB * NN * NN];
__device__ __half g_kerl[(size_t)BB * NN * NN];
__device__ __half g_gh [(size_t)MTOT * EE];
__device__ __half g_gl [(size_t)MTOT * EE];
__device__ __half g_ow [(size_t)DD * EE];

// ---------------- helpers -----------------------------------------------------
__device__ __forceinline__ uint32_t smem_u32(const void* p) {
    uint32_t a;
    asm("{ .reg .u64 t; cvta.to.shared.u64 t, %1; cvt.u32.u64 %0, t; }" : "=r"(a) : "l"(p));
    return a;
}
__device__ __forceinline__ void ldmx4(uint32_t* r, uint32_t a) {
    asm volatile("ldmatrix.sync.aligned.m8n8.x4.shared.b16 {%0,%1,%2,%3}, [%4];"
        : "=r"(r[0]), "=r"(r[1]), "=r"(r[2]), "=r"(r[3]) : "r"(a));
}
__device__ __forceinline__ void mma16816(float* c, const uint32_t* a,
                                         uint32_t b0, uint32_t b1) {
    asm volatile("mma.sync.aligned.m16n8k16.row.col.f32.f16.f16.f32 "
        "{%0,%1,%2,%3}, {%4,%5,%6,%7}, {%8,%9}, {%0,%1,%2,%3};"
        : "+f"(c[0]), "+f"(c[1]), "+f"(c[2]), "+f"(c[3])
        : "r"(a[0]), "r"(a[1]), "r"(a[2]), "r"(a[3]), "r"(b0), "r"(b1));
}
__device__ __forceinline__ void cp16(uint32_t dst, const void* src) {
    asm volatile("cp.async.cg.shared.global [%0], [%1], 16;" :: "r"(dst), "l"(src) : "memory");
}
#define CP_COMMIT() asm volatile("cp.async.commit_group;" ::: "memory")
#define CP_WAIT2()  asm volatile("cp.async.wait_group 2;"  ::: "memory")
#define CP_WAIT1()  asm volatile("cp.async.wait_group 1;"  ::: "memory")
#define CP_WAIT0()  asm volatile("cp.async.wait_group 0;"  ::: "memory")

// stage layout: A-hi 16K | A-lo 16K | B 16K  = 48 KB, 3 stages = 144 KB
#define STAGE_BYTES 49152
#define OFF_AH 0
#define OFF_AL 16384
#define OFF_B  32768
#define NSTAGE 3
#define SMEM_BYTES  (NSTAGE * STAGE_BYTES)

// load one 128x64(fp16) tile chunk (16 KB) into SW128-swizzled smem, 256 thr
__device__ __forceinline__ void ld_tile(uint32_t dst, const __half* src,
                                        int ld_elem, size_t kb0, int tid) {
    const char* sb = (const char*)src + kb0;
#pragma unroll
    for (int it = 0; it < 4; ++it) {
        int L = tid * 16 + it * 4096;
        int row = L >> 7, kb = L & 127;
        cp16(dst + (L ^ ((L >> 3) & 0x70)),
             sb + (size_t)row * ((size_t)ld_elem * 2) + kb);
    }
}

// ---------------- fp16 2-product split MMA GEMM core ---------------------------
// C(128x128 fp32) = (Ah + Al) * B^T.  A 128xK split fp16 (lda), B 128xK fp16 (ldb).
// 8 warps 4(M)x2(N), warp tile 32x64. Epilogue f(row, col, val), tile-relative.
template <class F>
__device__ __forceinline__ void mma_gemm(
    const __half* __restrict__ Ah, const __half* __restrict__ Al, int lda,
    const __half* __restrict__ B, int ldb,
    int K, F f)
{
    extern __shared__ char smem[];
    const uint32_t sbase = smem_u32(smem);
    const int tid = threadIdx.x;
    const int lane = tid & 31;
    const int wid = tid >> 5;
    const int wm = wid >> 1, wn = wid & 1;

    float c[2][8][4];
#pragma unroll
    for (int i = 0; i < 2; ++i)
#pragma unroll
        for (int j = 0; j < 8; ++j)
#pragma unroll
            for (int e = 0; e < 4; ++e) c[i][j][e] = 0.f;

    const int NCH = K >> 6;
    const int lhalf = (lane >> 4) << 4;
    const int arow  = wm * 32 + (lane & 15);
    const int brow  = wn * 64 + (lane & 15);

#define LOAD_CHUNK(CC, ST)                                                    \
    {                                                                         \
        uint32_t st_ = sbase + (ST) * STAGE_BYTES;                            \
        size_t kb0_ = (size_t)(CC) * 128;                                     \
        ld_tile(st_ + OFF_AH, Ah, lda, kb0_, tid);                            \
        ld_tile(st_ + OFF_AL, Al, lda, kb0_, tid);                            \
        ld_tile(st_ + OFF_B,  B,  ldb, kb0_, tid);                            \
    }

    LOAD_CHUNK(0, 0); CP_COMMIT();
    LOAD_CHUNK(1, 1); CP_COMMIT();

    int st_idx = 0;
    for (int cc = 0; cc < NCH; ++cc) {
        if (cc + 2 < NCH) {
            int ld_st = st_idx + 2 >= NSTAGE ? st_idx + 2 - NSTAGE : st_idx + 2;
            LOAD_CHUNK(cc + 2, ld_st);
            CP_COMMIT();
            CP_WAIT2();
        } else if (cc + 2 == NCH) {
            CP_WAIT1();
        } else {
            CP_WAIT0();
        }
        __syncthreads();

        const uint32_t st = sbase + st_idx * STAGE_BYTES;
#pragma unroll
        for (int ks = 0; ks < 4; ++ks) {
            const int kb = ks * 32 + lhalf;
            uint32_t ah[2][4], al[2][4];
#pragma unroll
            for (int mt = 0; mt < 2; ++mt) {
                uint32_t off = (uint32_t)(arow + mt * 16) * 128 + kb;
                off ^= (off >> 3) & 0x70;
                ldmx4(ah[mt], st + OFF_AH + off);
                ldmx4(al[mt], st + OFF_AL + off);
            }
#pragma unroll
            for (int np = 0; np < 4; ++np) {
                uint32_t bh[4];
                uint32_t off = (uint32_t)(brow + np * 16) * 128 + kb;
                off ^= (off >> 3) & 0x70;
                ldmx4(bh, st + OFF_B + off);
#pragma unroll
                for (int mt = 0; mt < 2; ++mt) {
                    float* c0 = c[mt][np * 2 + 0];
                    float* c1 = c[mt][np * 2 + 1];
                    mma16816(c0, ah[mt], bh[0], bh[2]);
                    mma16816(c0, al[mt], bh[0], bh[2]);
                    mma16816(c1, ah[mt], bh[1], bh[3]);
                    mma16816(c1, al[mt], bh[1], bh[3]);
                }
            }
        }
        __syncthreads();
        st_idx = st_idx + 1 >= NSTAGE ? 0 : st_idx + 1;
    }
#undef LOAD_CHUNK

    const int gID = lane >> 2, tg = lane & 3;
#pragma unroll
    for (int mt = 0; mt < 2; ++mt)
#pragma unroll
        for (int j = 0; j < 8; ++j) {
            int row = wm * 32 + mt * 16 + gID;
            int col = wn * 64 + j * 8 + tg * 2;
            f(row,     col,     c[mt][j][0]);
            f(row,     col + 1, c[mt][j][1]);
            f(row + 8, col,     c[mt][j][2]);
            f(row + 8, col + 1, c[mt][j][3]);
        }
}

// ---------------- LayerNorm -> fp16 hi/lo --------------------------------------
__global__ __launch_bounds__(256) void ln_kernel(const float* __restrict__ x,
                                                 const float* __restrict__ w,
                                                 const float* __restrict__ b)
{
    int row = blockIdx.x;
    int tid = threadIdx.x;
    float4 v = ((const float4*)(x + (size_t)row * DD))[tid];
    float s  = v.x + v.y + v.z + v.w;
    float ss = v.x*v.x + v.y*v.y + v.z*v.z + v.w*v.w;
#pragma unroll
    for (int o = 16; o; o >>= 1) {
        s  += __shfl_xor_sync(0xffffffffu, s , o);
        ss += __shfl_xor_sync(0xffffffffu, ss, o);
    }
    __shared__ float sh_s[8], sh_ss[8];
    int warp = tid >> 5;
    if ((tid & 31) == 0) { sh_s[warp] = s; sh_ss[warp] = ss; }
    __syncthreads();
    if (tid == 0) {
        float ts = 0.f, tss = 0.f;
#pragma unroll
        for (int i = 0; i < 8; ++i) { ts += sh_s[i]; tss += sh_ss[i]; }
        sh_s[0] = ts; sh_ss[0] = tss;
    }
    __syncthreads();
    float mean = sh_s[0] * (1.0f / DD);
    float var  = sh_ss[0] * (1.0f / DD) - mean * mean;
    float rs   = rsqrtf(var + 1e-5f);
    float4 wv = ((const float4*)w)[tid];
    float4 bv = ((const float4*)b)[tid];
    float o0 = (v.x - mean) * rs * wv.x + bv.x;
    float o1 = (v.y - mean) * rs * wv.y + bv.y;
    float o2 = (v.z - mean) * rs * wv.z + bv.z;
    float o3 = (v.w - mean) * rs * wv.w + bv.w;
    size_t eb = (size_t)row * DD + tid * 4;
    __half h0 = __float2half_rn(o0), h1 = __float2half_rn(o1);
    __half h2 = __float2half_rn(o2), h3 = __float2half_rn(o3);
    __half2 hA; hA.x = h0; hA.y = h1;
    __half2 hB; hB.x = h2; hB.y = h3;
    ((__half2*)(g_xnh + eb))[0] = hA;
    ((__half2*)(g_xnh + eb))[1] = hB;
    __half2 lA, lB;
    lA.x = __float2half_rn(o0 - __half2float(h0));
    lA.y = __float2half_rn(o1 - __half2float(h1));
    lB.x = __float2half_rn(o2 - __half2float(h2));
    lB.y = __float2half_rn(o3 - __half2float(h3));
    ((__half2*)(g_xnl + eb))[0] = lA;
    ((__half2*)(g_xnl + eb))[1] = lB;
}

// ---------------- fp32 -> fp16 convert ------------------------------------------
__global__ __launch_bounds__(256) void convert_kernel(const float* __restrict__ s,
                                                      __half* __restrict__ d,
                                                      int n4)
{
    int i = blockIdx.x * blockDim.x + threadIdx.x;
    if (i >= n4) return;
    float4 v = ((const float4*)s)[i];
    __half2 a; a.x = __float2half_rn(v.x); a.y = __float2half_rn(v.y);
    __half2 b; b.x = __float2half_rn(v.z); b.y = __float2half_rn(v.w);
    ((__half2*)d)[2 * i]     = a;
    ((__half2*)d)[2 * i + 1] = b;
}

// ---------------- GEMM1: uv = silu(xn @ uv_w^T + uv_b) --------------------------
__global__ __launch_bounds__(256, 1) void gemm_uv_mma(const float* __restrict__ uv_b)
{
    const int m0 = blockIdx.y * 128, n0 = blockIdx.x * 128;
    mma_gemm(g_xnh + (size_t)m0 * DD, g_xnl + (size_t)m0 * DD, DD,
             g_wuv + (size_t)n0 * DD, DD, DD,
        [&](int r, int cidx, float v) {
            int row = m0 + r, col = n0 + cidx;
            float t = v + uv_b[col];
            g_uv[(size_t)row * FF + col] = t / (1.f + expf(-t));
        });
}

// ---------------- V transpose -> fp16: vt[bt][e][n] ------------------------------
__global__ __launch_bounds__(256) void splitv_kernel()
{
    __shared__ float s[32][33];
    const int bt = blockIdx.z;
    const int k0 = blockIdx.y * 32, n0 = blockIdx.x * 32;
    const int tx = threadIdx.x, ty = threadIdx.y;   // (32, 8)
#pragma unroll
    for (int i = 0; i < 4; ++i) {
        int k = k0 + ty + i * 8;
        s[ty + i * 8][tx] = g_uv[((size_t)bt * NN + k) * FF + EE + n0 + tx];
    }
    __syncthreads();
#pragma unroll
    for (int i = 0; i < 4; ++i) {
        int n = n0 + ty + i * 8;
        g_vt[((size_t)bt * EE + n) * NN + k0 + tx] =
            __float2half_rn(s[tx][ty + i * 8]);
    }
}

// ---------------- gamma/beta + RoPE -> q, k --------------------------------------
__global__ void rope_kernel(const float* __restrict__ gamma,
                            const float* __restrict__ beta)
{
    const int row = blockIdx.x;
    const int s   = threadIdx.x;       // 0..63
    const int n   = row & (NN - 1);
    const float* base = g_uv + (size_t)row * FF + 2 * EE;
    const float b1 = base[s];
    const float b2 = base[s + 64];
    const float inv_freq = powf(10000.0f, (float)s * (1.0f / 64.0f));
    const float arg = (float)n * inv_freq;
    const float sn = sinf(arg);
    const float cs = cosf(arg);
#pragma unroll
    for (int h = 0; h < 2; ++h) {
        const float x1 = b1 * gamma[h * SS + s]      + beta[h * SS + s];
        const float x2 = b2 * gamma[h * SS + s + 64] + beta[h * SS + s + 64];
        float* dst = (h == 0 ? g_q : g_k) + (size_t)row * SS;
        dst[s]      = x1 * cs - x2 * sn;
        dst[s + 64] = x2 * cs + x1 * sn;
    }
}

// ---------------- qk SGEMM (fp32) + bias + relu^2 -> ker fp16 hi/lo --------------
__device__ __forceinline__ void gemm_abt_f32(const float* __restrict__ A,
                                             const float* __restrict__ B_,
                                             int K, int lda, int ldb,
                                             float acc[8][8])
{
    __shared__ float As[8][128];
    __shared__ float Bs[8][128];
    const int tid  = threadIdx.x;
    const int tx   = tid & 15, ty = tid >> 4;
    const int lrow = tid >> 1;
    const int lcol = (tid & 1) << 2;
    const float* Ap = A  + (size_t)lrow * lda + lcol;
    const float* Bp = B_ + (size_t)lrow * ldb + lcol;
#pragma unroll
    for (int i = 0; i < 8; ++i)
#pragma unroll
        for (int j = 0; j < 8; ++j) acc[i][j] = 0.f;
    for (int k0 = 0; k0 < K; k0 += 8) {
        float4 a4 = *(const float4*)(Ap + k0);
        float4 b4 = *(const float4*)(Bp + k0);
        __syncthreads();
        As[lcol+0][lrow] = a4.x; As[lcol+1][lrow] = a4.y;
        As[lcol+2][lrow] = a4.z; As[lcol+3][lrow] = a4.w;
        Bs[lcol+0][lrow] = b4.x; Bs[lcol+1][lrow] = b4.y;
        Bs[lcol+2][lrow] = b4.z; Bs[lcol+3][lrow] = b4.w;
        __syncthreads();
#pragma unroll
        for (int k = 0; k < 8; ++k) {
            float ar[8], br[8];
            *(float4*)(ar)     = *(const float4*)(&As[k][ty*8]);
            *(float4*)(ar + 4) = *(const float4*)(&As[k][ty*8 + 4]);
            *(float4*)(br)     = *(const float4*)(&Bs[k][tx*8]);
            *(float4*)(br + 4) = *(const float4*)(&Bs[k][tx*8 + 4]);
#pragma unroll
            for (int i = 0; i < 8; ++i)
#pragma unroll
                for (int j = 0; j < 8; ++j)
                    acc[i][j] = fmaf(ar[i], br[j], acc[i][j]);
        }
    }
}

__global__ __launch_bounds__(256) void qk_kernel(const float* __restrict__ w_rel)
{
    float acc[8][8];
    const int bt = blockIdx.z;
    const int m0 = blockIdx.y * 128, n0 = blockIdx.x * 128;
    gemm_abt_f32(g_q + ((size_t)bt * NN + m0) * SS,
                 g_k + ((size_t)bt * NN + n0) * SS, SS, SS, SS, acc);
    const int tx = threadIdx.x & 15, ty = threadIdx.x >> 4;
#pragma unroll
    for (int i = 0; i < 8; ++i) {
        const int row = m0 + ty * 8 + i;
#pragma unroll
        for (int j = 0; j < 8; ++j) {
            const int col = n0 + tx * 8 + j;
            float v = acc[i][j] * (1.0f / 512.0f) + w_rel[col - row + 511];
            float r = fmaxf(v, 0.f);
            float kv = r * r;
            __half h = __float2half_rn(kv);
            size_t idx = ((size_t)bt * NN + row) * NN + col;
            g_kerh[idx] = h;
            g_kerl[idx] = __float2half_rn(kv - __half2float(h));
        }
    }
}

// ---------------- kv: g = (ker @ V) * u  -----------------------------------------
__global__ __launch_bounds__(256, 1) void kv_mma()
{
    const int bt = blockIdx.z;
    const int m0 = blockIdx.y * 128, n0 = blockIdx.x * 128;
    const size_t rbase = (size_t)bt * NN;
    mma_gemm(g_kerh + (rbase + m0) * NN, g_kerl + (rbase + m0) * NN, NN,
             g_vt + ((size_t)bt * EE + n0) * NN, NN, NN,
        [&](int r, int cidx, float v) {
            size_t grow = rbase + m0 + r;
            int col = n0 + cidx;
            float g = g_uv[grow * FF + col] * v;
            __half h = __float2half_rn(g);
            g_gh[grow * EE + col] = h;
            g_gl[grow * EE + col] = __float2half_rn(g - __half2float(h));
        });
}

// ---------------- out = g @ o_w^T + o_b + shortcut --------------------------------
__global__ __launch_bounds__(256, 1) void out_mma(const float* __restrict__ o_b,
                                                  const float* __restrict__ x,
                                                  float* __restrict__ out)
{
    const int m0 = blockIdx.y * 128, n0 = blockIdx.x * 128;
    mma_gemm(g_gh + (size_t)m0 * EE, g_gl + (size_t)m0 * EE, EE,
             g_ow + (size_t)n0 * EE, EE, EE,
        [&](int r, int cidx, float v) {
            int row = m0 + r, col = n0 + cidx;
            out[(size_t)row * DD + col] =
                v + o_b[col] + x[(size_t)row * DD + col];
        });
}

// ---------------- launch ------------------------------------------------------------
extern "C" void kernel_launch(void* const* d_in, const int* in_sizes, int n_in,
                              void* d_out, int out_size)
{
    const float* x     = (const float*)d_in[0];
    const float* ln_w  = (const float*)d_in[1];
    const float* ln_b  = (const float*)d_in[2];
    const float* uv_w  = (const float*)d_in[3];
    const float* uv_b  = (const float*)d_in[4];
    const float* gamma = (const float*)d_in[5];
    const float* beta  = (const float*)d_in[6];
    const float* o_w   = (const float*)d_in[7];
    const float* o_b   = (const float*)d_in[8];
    const float* w_rel = (const float*)d_in[9];
    float* out = (float*)d_out;

    cudaFuncSetAttribute(gemm_uv_mma, cudaFuncAttributeMaxDynamicSharedMemorySize, SMEM_BYTES);
    cudaFuncSetAttribute(kv_mma,      cudaFuncAttributeMaxDynamicSharedMemorySize, SMEM_BYTES);
    cudaFuncSetAttribute(out_mma,     cudaFuncAttributeMaxDynamicSharedMemorySize, SMEM_BYTES);

    __half *wuv, *ow;
    cudaGetSymbolAddress((void**)&wuv, g_wuv);
    cudaGetSymbolAddress((void**)&ow,  g_ow);

    ln_kernel<<<MTOT, 256>>>(x, ln_w, ln_b);
    convert_kernel<<<(FF * DD / 4 + 255) / 256, 256>>>(uv_w, wuv, FF * DD / 4);
    convert_kernel<<<(DD * EE / 4 + 255) / 256, 256>>>(o_w, ow, DD * EE / 4);
    gemm_uv_mma<<<dim3(FF / 128, MTOT / 128), 256, SMEM_BYTES>>>(uv_b);
    splitv_kernel<<<dim3(EE / 32, NN / 32, BB), dim3(32, 8)>>>();
    rope_kernel<<<MTOT, 64>>>(gamma, beta);
    qk_kernel<<<dim3(NN / 128, NN / 128, BB), 256>>>(w_rel);
    kv_mma<<<dim3(EE / 128, NN / 128, BB), 256, SMEM_BYTES>>>();
    out_mma<<<dim3(DD / 128, MTOT / 128), 256, SMEM_BYTES>>>(o_b, x, out);
}

// round 6
// speedup vs baseline: 1.6836x; 1.2491x over previous
#include <cuda_runtime.h>
#include <cuda_fp16.h>
#include <math.h>
#include <stdint.h>

#define BB     16
#define NN     512
#define DD     1024
#define EE     2048
#define SS     128
#define FF     4224
#define MTOT   8192

// ---------------- scratch ----------------------------------------------------
__device__ __half g_xnh[(size_t)MTOT * DD];
__device__ __half g_xnl[(size_t)MTOT * DD];
__device__ __half g_wuv[(size_t)FF * DD];
__device__ float  g_uv [(size_t)MTOT * FF];
__device__ __half g_vt [(size_t)BB * EE * NN];
__device__ float  g_q  [(size_t)MTOT * SS];
__device__ float  g_k  [(size_t)MTOT * SS];
__device__ __half g_kerh[(size_t)BB * NN * NN];
__device__ __half g_kerl[(size_t)BB * NN * NN];
__device__ __half g_gh [(size_t)MTOT * EE];
__device__ __half g_gl [(size_t)MTOT * EE];
__device__ __half g_ow [(size_t)DD * EE];

// ---------------- helpers -----------------------------------------------------
__device__ __forceinline__ uint32_t smem_u32(const void* p) {
    uint32_t a;
    asm("{ .reg .u64 t; cvta.to.shared.u64 t, %1; cvt.u32.u64 %0, t; }" : "=r"(a) : "l"(p));
    return a;
}
__device__ __forceinline__ void ldmx4(uint32_t* r, uint32_t a) {
    asm volatile("ldmatrix.sync.aligned.m8n8.x4.shared.b16 {%0,%1,%2,%3}, [%4];"
        : "=r"(r[0]), "=r"(r[1]), "=r"(r[2]), "=r"(r[3]) : "r"(a));
}
__device__ __forceinline__ void mma16816(float* c, const uint32_t* a,
                                         uint32_t b0, uint32_t b1) {
    asm volatile("mma.sync.aligned.m16n8k16.row.col.f32.f16.f16.f32 "
        "{%0,%1,%2,%3}, {%4,%5,%6,%7}, {%8,%9}, {%0,%1,%2,%3};"
        : "+f"(c[0]), "+f"(c[1]), "+f"(c[2]), "+f"(c[3])
        : "r"(a[0]), "r"(a[1]), "r"(a[2]), "r"(a[3]), "r"(b0), "r"(b1));
}
__device__ __forceinline__ void cp16(uint32_t dst, const void* src) {
    asm volatile("cp.async.cg.shared.global [%0], [%1], 16;" :: "r"(dst), "l"(src) : "memory");
}
#define CP_COMMIT() asm volatile("cp.async.commit_group;" ::: "memory")
#define CP_WAIT1()  asm volatile("cp.async.wait_group 1;"  ::: "memory")
#define CP_WAIT0()  asm volatile("cp.async.wait_group 0;"  ::: "memory")

// stage layout: A-hi 16K | A-lo 16K | B 16K = 48 KB, 2 stages = 96 KB (2 CTAs/SM)
#define STAGE_BYTES 49152
#define OFF_AH 0
#define OFF_AL 16384
#define OFF_B  32768
#define NSTAGE 2
#define SMEM_BYTES  (NSTAGE * STAGE_BYTES)

// load one 128x64(fp16) tile chunk (16 KB) into SW128-swizzled smem, 256 thr
__device__ __forceinline__ void ld_tile(uint32_t dst, const __half* src,
                                        int ld_elem, size_t kb0, int tid) {
    const char* sb = (const char*)src + kb0;
#pragma unroll
    for (int it = 0; it < 4; ++it) {
        int L = tid * 16 + it * 4096;
        int row = L >> 7, kb = L & 127;
        cp16(dst + (L ^ ((L >> 3) & 0x70)),
             sb + (size_t)row * ((size_t)ld_elem * 2) + kb);
    }
}

// ---------------- fp16 2-product split MMA GEMM core ---------------------------
// C(128x128 fp32) = (Ah + Al) * B^T.  A 128xK split fp16 (lda), B 128xK fp16 (ldb).
// 8 warps 4(M)x2(N), warp tile 32x64. Epilogue f(row, col, val), tile-relative.
template <class F>
__device__ __forceinline__ void mma_gemm(
    const __half* __restrict__ Ah, const __half* __restrict__ Al, int lda,
    const __half* __restrict__ B, int ldb,
    int K, F f)
{
    extern __shared__ char smem[];
    const uint32_t sbase = smem_u32(smem);
    const int tid = threadIdx.x;
    const int lane = tid & 31;
    const int wid = tid >> 5;
    const int wm = wid >> 1, wn = wid & 1;

    float c[2][8][4];
#pragma unroll
    for (int i = 0; i < 2; ++i)
#pragma unroll
        for (int j = 0; j < 8; ++j)
#pragma unroll
            for (int e = 0; e < 4; ++e) c[i][j][e] = 0.f;

    const int NCH = K >> 6;
    const int lhalf = (lane >> 4) << 4;
    const int arow  = wm * 32 + (lane & 15);
    const int brow  = wn * 64 + (lane & 15);

#define LOAD_CHUNK(CC, ST)                                                    \
    {                                                                         \
        uint32_t st_ = sbase + (ST) * STAGE_BYTES;                            \
        size_t kb0_ = (size_t)(CC) * 128;                                     \
        ld_tile(st_ + OFF_AH, Ah, lda, kb0_, tid);                            \
        ld_tile(st_ + OFF_AL, Al, lda, kb0_, tid);                            \
        ld_tile(st_ + OFF_B,  B,  ldb, kb0_, tid);                            \
    }

    LOAD_CHUNK(0, 0); CP_COMMIT();

    for (int cc = 0; cc < NCH; ++cc) {
        if (cc + 1 < NCH) {
            LOAD_CHUNK(cc + 1, (cc + 1) & 1);
            CP_COMMIT();
            CP_WAIT1();
        } else {
            CP_WAIT0();
        }
        __syncthreads();

        const uint32_t st = sbase + (cc & 1) * STAGE_BYTES;
#pragma unroll
        for (int ks = 0; ks < 4; ++ks) {
            const int kb = ks * 32 + lhalf;
            uint32_t ah[2][4], al[2][4];
#pragma unroll
            for (int mt = 0; mt < 2; ++mt) {
                uint32_t off = (uint32_t)(arow + mt * 16) * 128 + kb;
                off ^= (off >> 3) & 0x70;
                ldmx4(ah[mt], st + OFF_AH + off);
                ldmx4(al[mt], st + OFF_AL + off);
            }
#pragma unroll
            for (int np = 0; np < 4; ++np) {
                uint32_t bh[4];
                uint32_t off = (uint32_t)(brow + np * 16) * 128 + kb;
                off ^= (off >> 3) & 0x70;
                ldmx4(bh, st + OFF_B + off);
#pragma unroll
                for (int mt = 0; mt < 2; ++mt) {
                    float* c0 = c[mt][np * 2 + 0];
                    float* c1 = c[mt][np * 2 + 1];
                    mma16816(c0, ah[mt], bh[0], bh[2]);
                    mma16816(c0, al[mt], bh[0], bh[2]);
                    mma16816(c1, ah[mt], bh[1], bh[3]);
                    mma16816(c1, al[mt], bh[1], bh[3]);
                }
            }
        }
        __syncthreads();
    }
#undef LOAD_CHUNK

    const int gID = lane >> 2, tg = lane & 3;
#pragma unroll
    for (int mt = 0; mt < 2; ++mt)
#pragma unroll
        for (int j = 0; j < 8; ++j) {
            int row = wm * 32 + mt * 16 + gID;
            int col = wn * 64 + j * 8 + tg * 2;
            f(row,     col,     c[mt][j][0]);
            f(row,     col + 1, c[mt][j][1]);
            f(row + 8, col,     c[mt][j][2]);
            f(row + 8, col + 1, c[mt][j][3]);
        }
}

// ---------------- LayerNorm -> fp16 hi/lo --------------------------------------
__global__ __launch_bounds__(256) void ln_kernel(const float* __restrict__ x,
                                                 const float* __restrict__ w,
                                                 const float* __restrict__ b)
{
    int row = blockIdx.x;
    int tid = threadIdx.x;
    float4 v = ((const float4*)(x + (size_t)row * DD))[tid];
    float s  = v.x + v.y + v.z + v.w;
    float ss = v.x*v.x + v.y*v.y + v.z*v.z + v.w*v.w;
#pragma unroll
    for (int o = 16; o; o >>= 1) {
        s  += __shfl_xor_sync(0xffffffffu, s , o);
        ss += __shfl_xor_sync(0xffffffffu, ss, o);
    }
    __shared__ float sh_s[8], sh_ss[8];
    int warp = tid >> 5;
    if ((tid & 31) == 0) { sh_s[warp] = s; sh_ss[warp] = ss; }
    __syncthreads();
    if (tid == 0) {
        float ts = 0.f, tss = 0.f;
#pragma unroll
        for (int i = 0; i < 8; ++i) { ts += sh_s[i]; tss += sh_ss[i]; }
        sh_s[0] = ts; sh_ss[0] = tss;
    }
    __syncthreads();
    float mean = sh_s[0] * (1.0f / DD);
    float var  = sh_ss[0] * (1.0f / DD) - mean * mean;
    float rs   = rsqrtf(var + 1e-5f);
    float4 wv = ((const float4*)w)[tid];
    float4 bv = ((const float4*)b)[tid];
    float o0 = (v.x - mean) * rs * wv.x + bv.x;
    float o1 = (v.y - mean) * rs * wv.y + bv.y;
    float o2 = (v.z - mean) * rs * wv.z + bv.z;
    float o3 = (v.w - mean) * rs * wv.w + bv.w;
    size_t eb = (size_t)row * DD + tid * 4;
    __half h0 = __float2half_rn(o0), h1 = __float2half_rn(o1);
    __half h2 = __float2half_rn(o2), h3 = __float2half_rn(o3);
    __half2 hA; hA.x = h0; hA.y = h1;
    __half2 hB; hB.x = h2; hB.y = h3;
    ((__half2*)(g_xnh + eb))[0] = hA;
    ((__half2*)(g_xnh + eb))[1] = hB;
    __half2 lA, lB;
    lA.x = __float2half_rn(o0 - __half2float(h0));
    lA.y = __float2half_rn(o1 - __half2float(h1));
    lB.x = __float2half_rn(o2 - __half2float(h2));
    lB.y = __float2half_rn(o3 - __half2float(h3));
    ((__half2*)(g_xnl + eb))[0] = lA;
    ((__half2*)(g_xnl + eb))[1] = lB;
}

// ---------------- fp32 -> fp16 convert ------------------------------------------
__global__ __launch_bounds__(256) void convert_kernel(const float* __restrict__ s,
                                                      __half* __restrict__ d,
                                                      int n4)
{
    int i = blockIdx.x * blockDim.x + threadIdx.x;
    if (i >= n4) return;
    float4 v = ((const float4*)s)[i];
    __half2 a; a.x = __float2half_rn(v.x); a.y = __float2half_rn(v.y);
    __half2 b; b.x = __float2half_rn(v.z); b.y = __float2half_rn(v.w);
    ((__half2*)d)[2 * i]     = a;
    ((__half2*)d)[2 * i + 1] = b;
}

// ---------------- GEMM1: uv = silu(xn @ uv_w^T + uv_b) --------------------------
__global__ __launch_bounds__(256, 2) void gemm_uv_mma(const float* __restrict__ uv_b)
{
    const int m0 = blockIdx.y * 128, n0 = blockIdx.x * 128;
    mma_gemm(g_xnh + (size_t)m0 * DD, g_xnl + (size_t)m0 * DD, DD,
             g_wuv + (size_t)n0 * DD, DD, DD,
        [&](int r, int cidx, float v) {
            int row = m0 + r, col = n0 + cidx;
            float t = v + uv_b[col];
            g_uv[(size_t)row * FF + col] = t / (1.f + expf(-t));
        });
}

// ---------------- V transpose -> fp16: vt[bt][e][n] ------------------------------
__global__ __launch_bounds__(256) void splitv_kernel()
{
    __shared__ float s[32][33];
    const int bt = blockIdx.z;
    const int k0 = blockIdx.y * 32, n0 = blockIdx.x * 32;
    const int tx = threadIdx.x, ty = threadIdx.y;   // (32, 8)
#pragma unroll
    for (int i = 0; i < 4; ++i) {
        int k = k0 + ty + i * 8;
        s[ty + i * 8][tx] = g_uv[((size_t)bt * NN + k) * FF + EE + n0 + tx];
    }
    __syncthreads();
#pragma unroll
    for (int i = 0; i < 4; ++i) {
        int n = n0 + ty + i * 8;
        g_vt[((size_t)bt * EE + n) * NN + k0 + tx] =
            __float2half_rn(s[tx][ty + i * 8]);
    }
}

// ---------------- gamma/beta + RoPE -> q, k --------------------------------------
__global__ void rope_kernel(const float* __restrict__ gamma,
                            const float* __restrict__ beta)
{
    const int row = blockIdx.x;
    const int s   = threadIdx.x;       // 0..63
    const int n   = row & (NN - 1);
    const float* base = g_uv + (size_t)row * FF + 2 * EE;
    const float b1 = base[s];
    const float b2 = base[s + 64];
    const float inv_freq = powf(10000.0f, (float)s * (1.0f / 64.0f));
    const float arg = (float)n * inv_freq;
    const float sn = sinf(arg);
    const float cs = cosf(arg);
#pragma unroll
    for (int h = 0; h < 2; ++h) {
        const float x1 = b1 * gamma[h * SS + s]      + beta[h * SS + s];
        const float x2 = b2 * gamma[h * SS + s + 64] + beta[h * SS + s + 64];
        float* dst = (h == 0 ? g_q : g_k) + (size_t)row * SS;
        dst[s]      = x1 * cs - x2 * sn;
        dst[s + 64] = x2 * cs + x1 * sn;
    }
}

// ---------------- qk SGEMM (fp32) + bias + relu^2 -> ker fp16 hi/lo --------------
__device__ __forceinline__ void gemm_abt_f32(const float* __restrict__ A,
                                             const float* __restrict__ B_,
                                             int K, int lda, int ldb,
                                             float acc[8][8])
{
    __shared__ float As[8][128];
    __shared__ float Bs[8][128];
    const int tid  = threadIdx.x;
    const int tx   = tid & 15, ty = tid >> 4;
    const int lrow = tid >> 1;
    const int lcol = (tid & 1) << 2;
    const float* Ap = A  + (size_t)lrow * lda + lcol;
    const float* Bp = B_ + (size_t)lrow * ldb + lcol;
#pragma unroll
    for (int i = 0; i < 8; ++i)
#pragma unroll
        for (int j = 0; j < 8; ++j) acc[i][j] = 0.f;
    for (int k0 = 0; k0 < K; k0 += 8) {
        float4 a4 = *(const float4*)(Ap + k0);
        float4 b4 = *(const float4*)(Bp + k0);
        __syncthreads();
        As[lcol+0][lrow] = a4.x; As[lcol+1][lrow] = a4.y;
        As[lcol+2][lrow] = a4.z; As[lcol+3][lrow] = a4.w;
        Bs[lcol+0][lrow] = b4.x; Bs[lcol+1][lrow] = b4.y;
        Bs[lcol+2][lrow] = b4.z; Bs[lcol+3][lrow] = b4.w;
        __syncthreads();
#pragma unroll
        for (int k = 0; k < 8; ++k) {
            float ar[8], br[8];
            *(float4*)(ar)     = *(const float4*)(&As[k][ty*8]);
            *(float4*)(ar + 4) = *(const float4*)(&As[k][ty*8 + 4]);
            *(float4*)(br)     = *(const float4*)(&Bs[k][tx*8]);
            *(float4*)(br + 4) = *(const float4*)(&Bs[k][tx*8 + 4]);
#pragma unroll
            for (int i = 0; i < 8; ++i)
#pragma unroll
                for (int j = 0; j < 8; ++j)
                    acc[i][j] = fmaf(ar[i], br[j], acc[i][j]);
        }
    }
}

__global__ __launch_bounds__(256) void qk_kernel(const float* __restrict__ w_rel)
{
    float acc[8][8];
    const int bt = blockIdx.z;
    const int m0 = blockIdx.y * 128, n0 = blockIdx.x * 128;
    gemm_abt_f32(g_q + ((size_t)bt * NN + m0) * SS,
                 g_k + ((size_t)bt * NN + n0) * SS, SS, SS, SS, acc);
    const int tx = threadIdx.x & 15, ty = threadIdx.x >> 4;
#pragma unroll
    for (int i = 0; i < 8; ++i) {
        const int row = m0 + ty * 8 + i;
#pragma unroll
        for (int j = 0; j < 8; ++j) {
            const int col = n0 + tx * 8 + j;
            float v = acc[i][j] * (1.0f / 512.0f) + w_rel[col - row + 511];
            float r = fmaxf(v, 0.f);
            float kv = r * r;
            __half h = __float2half_rn(kv);
            size_t idx = ((size_t)bt * NN + row) * NN + col;
            g_kerh[idx] = h;
            g_kerl[idx] = __float2half_rn(kv - __half2float(h));
        }
    }
}

// ---------------- kv: g = (ker @ V) * u  -----------------------------------------
__global__ __launch_bounds__(256, 2) void kv_mma()
{
    const int bt = blockIdx.z;
    const int m0 = blockIdx.y * 128, n0 = blockIdx.x * 128;
    const size_t rbase = (size_t)bt * NN;
    mma_gemm(g_kerh + (rbase + m0) * NN, g_kerl + (rbase + m0) * NN, NN,
             g_vt + ((size_t)bt * EE + n0) * NN, NN, NN,
        [&](int r, int cidx, float v) {
            size_t grow = rbase + m0 + r;
            int col = n0 + cidx;
            float g = g_uv[grow * FF + col] * v;
            __half h = __float2half_rn(g);
            g_gh[grow * EE + col] = h;
            g_gl[grow * EE + col] = __float2half_rn(g - __half2float(h));
        });
}

// ---------------- out = g @ o_w^T + o_b + shortcut --------------------------------
__global__ __launch_bounds__(256, 2) void out_mma(const float* __restrict__ o_b,
                                                  const float* __restrict__ x,
                                                  float* __restrict__ out)
{
    const int m0 = blockIdx.y * 128, n0 = blockIdx.x * 128;
    mma_gemm(g_gh + (size_t)m0 * EE, g_gl + (size_t)m0 * EE, EE,
             g_ow + (size_t)n0 * EE, EE, EE,
        [&](int r, int cidx, float v) {
            int row = m0 + r, col = n0 + cidx;
            out[(size_t)row * DD + col] =
                v + o_b[col] + x[(size_t)row * DD + col];
        });
}

// ---------------- launch ------------------------------------------------------------
extern "C" void kernel_launch(void* const* d_in, const int* in_sizes, int n_in,
                              void* d_out, int out_size)
{
    const float* x     = (const float*)d_in[0];
    const float* ln_w  = (const float*)d_in[1];
    const float* ln_b  = (const float*)d_in[2];
    const float* uv_w  = (const float*)d_in[3];
    const float* uv_b  = (const float*)d_in[4];
    const float* gamma = (const float*)d_in[5];
    const float* beta  = (const float*)d_in[6];
    const float* o_w   = (const float*)d_in[7];
    const float* o_b   = (const float*)d_in[8];
    const float* w_rel = (const float*)d_in[9];
    float* out = (float*)d_out;

    cudaFuncSetAttribute(gemm_uv_mma, cudaFuncAttributeMaxDynamicSharedMemorySize, SMEM_BYTES);
    cudaFuncSetAttribute(kv_mma,      cudaFuncAttributeMaxDynamicSharedMemorySize, SMEM_BYTES);
    cudaFuncSetAttribute(out_mma,     cudaFuncAttributeMaxDynamicSharedMemorySize, SMEM_BYTES);

    __half *wuv, *ow;
    cudaGetSymbolAddress((void**)&wuv, g_wuv);
    cudaGetSymbolAddress((void**)&ow,  g_ow);

    ln_kernel<<<MTOT, 256>>>(x, ln_w, ln_b);
    convert_kernel<<<(FF * DD / 4 + 255) / 256, 256>>>(uv_w, wuv, FF * DD / 4);
    convert_kernel<<<(DD * EE / 4 + 255) / 256, 256>>>(o_w, ow, DD * EE / 4);
    gemm_uv_mma<<<dim3(FF / 128, MTOT / 128), 256, SMEM_BYTES>>>(uv_b);
    splitv_kernel<<<dim3(EE / 32, NN / 32, BB), dim3(32, 8)>>>();
    rope_kernel<<<MTOT, 64>>>(gamma, beta);
    qk_kernel<<<dim3(NN / 128, NN / 128, BB), 256>>>(w_rel);
    kv_mma<<<dim3(EE / 128, NN / 128, BB), 256, SMEM_BYTES>>>();
    out_mma<<<dim3(DD / 128, MTOT / 128), 256, SMEM_BYTES>>>(o_b, x, out);
}